// round 6
// baseline (speedup 1.0000x reference)
#include <cuda_runtime.h>

#define HH 96
#define WW 96
#define NPIX (HH*WW)

// ---------------- scratch (static device globals; no allocation) ----------------
__device__ float g_x[4*64*NPIX];      // staged x for the 4 (dir,batch) lanes
__device__ float g_h[4*64*NPIX];      // hidden state
__device__ float g_c[4*64*NPIX];      // cell state
__device__ float g_comb[4*64*NPIX];   // fuse conv output
__device__ float g_om[4*216*NPIX];    // offset/mask conv output
__device__ float g_samp[4*576*NPIX];  // DCN sampled im2col matrix [n][cin*9+kk][pix]
__device__ float g_fused[4*128*NPIX]; // DCN output (relu)
__device__ float g_cc[4*256*NPIX];    // gate conv output
__device__ float g_fwd[10*64*NPIX];   // fwd hidden over time  [t*2+b]
__device__ float g_bwd[10*64*NPIX];   // bwd hidden over time  [t*2+b]

// ---------------- packed fp32x2 FMA ----------------
__device__ __forceinline__ void ffma2(unsigned long long& d, unsigned long long a, unsigned long long b) {
    asm("fma.rn.f32x2 %0, %1, %2, %0;" : "+l"(d) : "l"(a), "l"(b));
}
__device__ __forceinline__ float lo32(unsigned long long v){ return __uint_as_float((unsigned)(v & 0xffffffffu)); }
__device__ __forceinline__ float hi32(unsigned long long v){ return __uint_as_float((unsigned)(v >> 32)); }
__device__ __forceinline__ float sigf(float x){ return 1.f / (1.f + __expf(-x)); }

// ---------------- implicit-GEMM conv / dense GEMM ----------------
// C[n][co][pix] = sum_k W[co][k] * B[k][pix] (+bias, opt relu)
// MODE 0: B = implicit im2col of conv3x3 over channel-concat(in0[cin0], in1[...])
//         k = cin*9 + (ky*3+kx), matching [Cout][Cin][3][3] weight layout.
// MODE 1: B = dense matrix in0 + n*s0, laid out [K][NPIX].
// OUTBT 1: n = t*2+b, output goes to out[(b*5+t)][co][pix] (final cat conv).
template<int COTILE, int MODE, int ACT, int OUTBT>
__global__ __launch_bounds__(COTILE*2) void gemm_k(
    const float* __restrict__ in0, long s0, int cin0,
    const float* __restrict__ in1, long s1,
    const float* __restrict__ wgt, const float* __restrict__ bias,
    float* __restrict__ out, int Cout, int K)
{
    constexpr int NT = COTILE * 2;     // 128 or 256 threads
    constexpr int BE = 1024 / NT;      // B elements loaded per thread per chunk
    __shared__ float As2[8][2*COTILE]; // A tile, each weight duplicated pairwise for f32x2
    __shared__ float Bs[8][128];

    const int tid = threadIdx.x;
    const int n   = blockIdx.z;
    const int p0  = blockIdx.x * 128;
    const int co0 = blockIdx.y * COTILE;
    const int tx  = tid & 15;   // 16 pixel groups of 8
    const int ty  = tid >> 4;   // cout groups of 8

    unsigned long long acc[8][4];
#pragma unroll
    for (int i = 0; i < 8; i++)
#pragma unroll
        for (int j = 0; j < 4; j++) acc[i][j] = 0ULL;

    const float* base0 = in0 + (long)n * s0;
    const float* base1 = (MODE == 0 && in1) ? (in1 + (long)n * s1) : (const float*)0;

    // A-load mapping: thread -> (cout row, 4 of the 8 k's)
    const int aco = tid % COTILE;
    const int ah  = (tid / COTILE) * 4;            // 0 or 4
    const bool arow_ok = (co0 + aco) < Cout;
    const float* wrow = wgt + (long)(co0 + aco) * K + ah;

    // B-load mapping: precompute per-element pixel coords and k-offset
    int bk[BE], bpy[BE], bpx[BE], bpp[BE];
#pragma unroll
    for (int i = 0; i < BE; i++) {
        int e = tid + i * NT;
        bk[i]  = e >> 7;
        int p  = e & 127;
        bpp[i] = p;
        int pg = p0 + p;
        int y  = pg / WW;
        bpy[i] = y;
        bpx[i] = pg - y * WW;
    }

    for (int kk0 = 0; kk0 < K; kk0 += 8) {
        float4 av = make_float4(0.f, 0.f, 0.f, 0.f);
        if (arow_ok) av = *(const float4*)(wrow + kk0);

        float bv[BE];
#pragma unroll
        for (int i = 0; i < BE; i++) {
            float v;
            if (MODE == 0) {
                int kg  = kk0 + bk[i];
                int cin = kg / 9;
                int r   = kg - cin * 9;
                int ky  = r / 3;
                int kx  = r - ky * 3;
                int iy  = bpy[i] + ky - 1;
                int ix  = bpx[i] + kx - 1;
                v = 0.f;
                if (iy >= 0 && iy < HH && ix >= 0 && ix < WW) {
                    const float* src = (cin < cin0) ? (base0 + (long)cin * NPIX)
                                                    : (base1 + (long)(cin - cin0) * NPIX);
                    v = __ldg(src + iy * WW + ix);
                }
            } else {
                v = __ldg(base0 + (long)(kk0 + bk[i]) * NPIX + p0 + bpp[i]);
            }
            bv[i] = v;
        }

        __syncthreads();   // previous chunk fully consumed
        {
            const float* avp = (const float*)&av;
#pragma unroll
            for (int j = 0; j < 4; j++) {
                float2 d; d.x = avp[j]; d.y = avp[j];
                *(float2*)&As2[ah + j][aco * 2] = d;
            }
        }
#pragma unroll
        for (int i = 0; i < BE; i++) {
            int e = tid + i * NT;
            Bs[e >> 7][e & 127] = bv[i];
        }
        __syncthreads();

#pragma unroll
        for (int k = 0; k < 8; k++) {
            ulonglong2 aq0 = *(const ulonglong2*)&As2[k][ty*16];
            ulonglong2 aq1 = *(const ulonglong2*)&As2[k][ty*16 + 4];
            ulonglong2 aq2 = *(const ulonglong2*)&As2[k][ty*16 + 8];
            ulonglong2 aq3 = *(const ulonglong2*)&As2[k][ty*16 + 12];
            ulonglong2 bq0 = *(const ulonglong2*)&Bs[k][tx*8];
            ulonglong2 bq1 = *(const ulonglong2*)&Bs[k][tx*8 + 4];
            unsigned long long aa[8] = {aq0.x, aq0.y, aq1.x, aq1.y, aq2.x, aq2.y, aq3.x, aq3.y};
            unsigned long long bb[4] = {bq0.x, bq0.y, bq1.x, bq1.y};
#pragma unroll
            for (int i = 0; i < 8; i++)
#pragma unroll
                for (int j = 0; j < 4; j++)
                    ffma2(acc[i][j], aa[i], bb[j]);
        }
    }

    // epilogue
#pragma unroll
    for (int i = 0; i < 8; i++) {
        int co = co0 + ty * 8 + i;
        if (co >= Cout) continue;
        float bsv = bias[co];
        long ob;
        if (OUTBT) {
            int b = n & 1, t = n >> 1;
            ob = ((long)(b * 5 + t) * Cout + co) * NPIX + p0 + tx * 8;
        } else {
            ob = ((long)n * Cout + co) * NPIX + p0 + tx * 8;
        }
        float4 o0, o1;
        o0.x = lo32(acc[i][0]) + bsv;  o0.y = hi32(acc[i][0]) + bsv;
        o0.z = lo32(acc[i][1]) + bsv;  o0.w = hi32(acc[i][1]) + bsv;
        o1.x = lo32(acc[i][2]) + bsv;  o1.y = hi32(acc[i][2]) + bsv;
        o1.z = lo32(acc[i][3]) + bsv;  o1.w = hi32(acc[i][3]) + bsv;
        if (ACT) {
            o0.x = fmaxf(o0.x, 0.f); o0.y = fmaxf(o0.y, 0.f);
            o0.z = fmaxf(o0.z, 0.f); o0.w = fmaxf(o0.w, 0.f);
            o1.x = fmaxf(o1.x, 0.f); o1.y = fmaxf(o1.y, 0.f);
            o1.z = fmaxf(o1.z, 0.f); o1.w = fmaxf(o1.w, 0.f);
        }
        *(float4*)(out + ob)     = o0;
        *(float4*)(out + ob + 4) = o1;
    }
}

// ---------------- stage x slices for the 4 lanes ----------------
// lane n: n<2 -> fwd, b=n, time t ; n>=2 -> bwd, b=n-2, time 4-t
__global__ void stage_x(const float* __restrict__ inp, int t)
{
    int id = blockIdx.x * blockDim.x + threadIdx.x;     // 4*64*NPIX threads
    int p  = id % NPIX;
    int r  = id / NPIX;
    int ch = r % 64;
    int n  = r / 64;
    int b  = n & 1;
    int ts = (n < 2) ? t : (4 - t);
    g_x[id] = inp[(((long)b * 5 + ts) * 64 + ch) * NPIX + p];
}

// ---------------- DCN bilinear sampler -> sampled im2col matrix ----------------
__global__ void dcn_sample(const float* __restrict__ om, const float* __restrict__ hbuf,
                           float* __restrict__ samp)
{
    int id = blockIdx.x * blockDim.x + threadIdx.x;     // 4*8*9*NPIX threads
    int p  = id % NPIX;
    int r  = id / NPIX;
    int kk = r % 9;  r /= 9;
    int g  = r % 8;
    int n  = r / 8;

    const float* omb = om + (long)n * 216 * NPIX;
    float offy = omb[((g * 9 + kk) * 2 + 0) * NPIX + p];
    float offx = omb[((g * 9 + kk) * 2 + 1) * NPIX + p];
    float m    = sigf(omb[(144 + g * 9 + kk) * NPIX + p]);

    int y  = p / WW;
    int x  = p - y * WW;
    int ky = kk / 3;
    int kx = kk - ky * 3;
    float py = (float)(y + ky - 1) + offy;
    float px = (float)(x + kx - 1) + offx;
    float fy = floorf(py), fx = floorf(px);
    float wy = py - fy,    wx = px - fx;
    int y0 = (int)fy, x0 = (int)fx;
    int y1 = y0 + 1,  x1 = x0 + 1;

    bool vy0 = (y0 >= 0) & (y0 < HH);
    bool vy1 = (y1 >= 0) & (y1 < HH);
    bool vx0 = (x0 >= 0) & (x0 < WW);
    bool vx1 = (x1 >= 0) & (x1 < WW);
    float w00 = (1.f - wy) * (1.f - wx) * (float)(vy0 && vx0);
    float w01 = (1.f - wy) * wx         * (float)(vy0 && vx1);
    float w10 = wy * (1.f - wx)         * (float)(vy1 && vx0);
    float w11 = wy * wx                 * (float)(vy1 && vx1);

    int cy0 = min(max(y0, 0), HH - 1), cy1 = min(max(y1, 0), HH - 1);
    int cx0 = min(max(x0, 0), WW - 1), cx1 = min(max(x1, 0), WW - 1);
    int i00 = cy0 * WW + cx0, i01 = cy0 * WW + cx1;
    int i10 = cy1 * WW + cx0, i11 = cy1 * WW + cx1;

    const float* hb = hbuf + ((long)n * 64 + g * 8) * NPIX;
    float* sb = samp + (long)n * 576 * NPIX + (long)(g * 8) * 9 * NPIX + (long)kk * NPIX + p;
#pragma unroll
    for (int cg = 0; cg < 8; cg++) {
        const float* f = hb + (long)cg * NPIX;
        float v = w00 * f[i00] + w01 * f[i01] + w10 * f[i10] + w11 * f[i11];
        sb[(long)cg * 9 * NPIX] = v * m;
    }
}

// ---------------- LSTM pointwise update ----------------
__global__ void lstm_k(const float* __restrict__ cc, float* __restrict__ hbuf,
                       float* __restrict__ cbuf, float* __restrict__ fwdb,
                       float* __restrict__ bwdb, int t)
{
    int id = blockIdx.x * blockDim.x + threadIdx.x;     // 4*64*NPIX threads
    int p  = id % NPIX;
    int r  = id / NPIX;
    int ch = r % 64;
    int n  = r / 64;

    const float* c4 = cc + (long)n * 256 * NPIX;
    float ci = c4[(      ch) * NPIX + p];
    float cf = c4[( 64 + ch) * NPIX + p];
    float co = c4[(128 + ch) * NPIX + p];
    float cg = c4[(192 + ch) * NPIX + p];

    long hi = ((long)n * 64 + ch) * NPIX + p;
    float c  = cbuf[hi];
    float c2 = sigf(cf) * c + sigf(ci) * tanhf(cg);
    float h2 = sigf(co) * tanhf(c2);
    cbuf[hi] = c2;
    hbuf[hi] = h2;

    long o = (long)ch * NPIX + p;
    if (n < 2) fwdb[(long)(t * 2 + n) * 64 * NPIX + o] = h2;
    else       bwdb[(long)((4 - t) * 2 + (n - 2)) * 64 * NPIX + o] = h2;
}

// ---------------- host orchestration (graph-capturable) ----------------
extern "C" void kernel_launch(void* const* d_in, const int* in_sizes, int n_in,
                              void* d_out, int out_size)
{
    (void)in_sizes; (void)n_in; (void)out_size;
    const float* inp    = (const float*)d_in[0];
    const float* fuse_w = (const float*)d_in[1];
    const float* fuse_b = (const float*)d_in[2];
    const float* om_w   = (const float*)d_in[3];
    const float* om_b   = (const float*)d_in[4];
    const float* dcn_w  = (const float*)d_in[5];
    const float* dcn_b  = (const float*)d_in[6];
    const float* conv_w = (const float*)d_in[7];
    const float* conv_b = (const float*)d_in[8];
    const float* cat_w  = (const float*)d_in[9];
    const float* cat_b  = (const float*)d_in[10];

    float *xb, *hb, *cb, *comb, *omb, *sb, *fub, *ccb, *fwdb, *bwdb;
    cudaGetSymbolAddress((void**)&xb,   g_x);
    cudaGetSymbolAddress((void**)&hb,   g_h);
    cudaGetSymbolAddress((void**)&cb,   g_c);
    cudaGetSymbolAddress((void**)&comb, g_comb);
    cudaGetSymbolAddress((void**)&omb,  g_om);
    cudaGetSymbolAddress((void**)&sb,   g_samp);
    cudaGetSymbolAddress((void**)&fub,  g_fused);
    cudaGetSymbolAddress((void**)&ccb,  g_cc);
    cudaGetSymbolAddress((void**)&fwdb, g_fwd);
    cudaGetSymbolAddress((void**)&bwdb, g_bwd);

    cudaMemsetAsync(hb, 0, sizeof(float) * 4 * 64 * NPIX);
    cudaMemsetAsync(cb, 0, sizeof(float) * 4 * 64 * NPIX);

    for (int t = 0; t < 5; t++) {
        stage_x<<<(4*64*NPIX)/256, 256>>>(inp, t);
        // combined = conv3x3(concat(x, h))  : Cout=64, K=128*9
        gemm_k<64, 0, 0, 0><<<dim3(72, 1, 4), 128>>>(xb, 64L*NPIX, 64, hb, 64L*NPIX,
                                                     fuse_w, fuse_b, comb, 64, 1152);
        // om = conv3x3(combined)            : Cout=216, K=64*9
        gemm_k<128, 0, 0, 0><<<dim3(72, 2, 4), 256>>>(comb, 64L*NPIX, 64, (const float*)0, 0,
                                                      om_w, om_b, omb, 216, 576);
        // DCN sampling -> sampled matrix [576][NPIX]
        dcn_sample<<<(4*8*9*NPIX)/256, 256>>>(omb, hb, sb);
        // fused = relu(W_dcn @ sampled + b) : Cout=128, K=576 (dense GEMM)
        gemm_k<128, 1, 1, 0><<<dim3(72, 1, 4), 256>>>(sb, 576L*NPIX, 0, (const float*)0, 0,
                                                      dcn_w, dcn_b, fub, 128, 576);
        // cc = conv3x3(fused)               : Cout=256, K=128*9
        gemm_k<128, 0, 0, 0><<<dim3(72, 2, 4), 256>>>(fub, 128L*NPIX, 128, (const float*)0, 0,
                                                      conv_w, conv_b, ccb, 256, 1152);
        // LSTM gates + state update + store into time buffers
        lstm_k<<<(4*64*NPIX)/256, 256>>>(ccb, hb, cb, fwdb, bwdb, t);
    }

    // out[b][t] = conv3x3(concat(fwd[t], bwd[t]))  over all 10 (t,b) pairs
    gemm_k<64, 0, 0, 1><<<dim3(72, 1, 10), 128>>>(fwdb, 64L*NPIX, 64, bwdb, 64L*NPIX,
                                                  cat_w, cat_b, (float*)d_out, 64, 1152);
}